// round 4
// baseline (speedup 1.0000x reference)
#include <cuda_runtime.h>

// Problem constants (match reference module)
namespace {
constexpr int kB = 32, kT = 200, kR = 4096, kC = 81;
constexpr float kIouTh = 0.7f;
constexpr int kThreads = 128;                 // 4 warps/block
constexpr int kIlp = 2;                       // proposals per thread
constexpr int kRPerChunk = kThreads * kIlp;   // 256 proposals per (b,chunk)
constexpr int kChunks = kR / kRPerChunk;      // 16
constexpr int kTH = kT / 2;                   // 100 GT boxes per half
constexpr int kMergeSlots = kB * kChunks;     // 512
constexpr int kNBlocks = kMergeSlots * 2;     // 1024 -> 6.92 blocks/SM, balanced
}

// Per-(b,chunk,half) argmax partials: (binter, bS, bidx_bits, pad)
__device__ float4 g_part[kNBlocks * kRPerChunk];          // 4 MB
__device__ unsigned int g_sync[kMergeSlots];              // pairwise rendezvous
__device__ float g_red[kMergeSlots][4];                   // merge-block partial sums
__device__ unsigned int g_done = 0;                       // finalize rendezvous

__device__ __forceinline__ float warp_sum(float v) {
#pragma unroll
    for (int o = 16; o > 0; o >>= 1) v += __shfl_down_sync(0xffffffffu, v, o);
    return v;
}

__global__ __launch_bounds__(kThreads) void rcnn_main(
    const float4* __restrict__ nms_reg,   // [B,R,4]
    const float4* __restrict__ rcnn_reg,  // [B,R,4]
    const float*  __restrict__ rcnn_cls,  // [B,R,C]
    const float4* __restrict__ bboxes,    // [B,T,4]
    const int*    __restrict__ classes,   // [B,T]
    float* __restrict__ out)              // [3]
{
    __shared__ float4 s_box[kTH];
    __shared__ float  s_area[kTH];

    const int slot = blockIdx.x >> 1;          // (b, chunk)
    const int half = blockIdx.x & 1;
    const int b = slot / kChunks;
    const int chunk = slot % kChunks;
    const int tid = threadIdx.x;

    // Load this block's half of the GT boxes
    for (int i = tid; i < kTH; i += kThreads) {
        float4 bb = bboxes[b * kT + half * kTH + i];
        s_box[i] = bb;
        s_area[i] = (bb.z - bb.x) * (bb.w - bb.y);
    }
    __syncthreads();

    // Strided proposal mapping spreads positives (r < T) over all chunks.
    int j[kIlp], r[kIlp];
    float4 a[kIlp];
    float areaA[kIlp], binter[kIlp], bS[kIlp];
    int bidx[kIlp];
#pragma unroll
    for (int i = 0; i < kIlp; i++) {
        j[i] = tid + i * kThreads;
        r[i] = chunk + kChunks * j[i];
        a[i] = nms_reg[b * kR + r[i]];
        areaA[i] = (a[i].z - a[i].x) * (a[i].w - a[i].y);
        binter[i] = 0.f;      // zero IoU -> keeps smallest t (first occurrence)
        bS[i] = 1.f;
        bidx[i] = half * kTH; // smallest t in this half
    }

    // ---- IoU argmax over this half's GT (division-free; S-form compare) ----
    // den = S - inter with S = areaA + ab, so
    //   inter/(S_b - binter) > binter/(S - inter)  <=>  inter*S_b > binter*S
    // (the -inter*binter terms cancel exactly). iw left unclamped: negative iw
    // gives inter <= 0 which can never win (binter >= 0, S > 0, S_b > 0).
#pragma unroll 4
    for (int t = 0; t < kTH; ++t) {
        float4 bb = s_box[t];
        float  ab = s_area[t];
#pragma unroll
        for (int i = 0; i < kIlp; i++) {
            float tt = fmaxf(a[i].x, bb.x);
            float ll = fmaxf(a[i].y, bb.y);
            float bo = fminf(a[i].z, bb.z);
            float rr = fminf(a[i].w, bb.w);
            float ih = fmaxf(bo - tt, 0.f);
            float iw = rr - ll;
            float inter = ih * iw;
            float S = areaA[i] + ab;
            bool upd = inter * bS[i] > binter[i] * S;
            binter[i] = upd ? inter : binter[i];
            bS[i]     = upd ? S     : bS[i];
            bidx[i]   = upd ? (half * kTH + t) : bidx[i];
        }
    }

    // ---- publish partials, rendezvous with sibling half ----
#pragma unroll
    for (int i = 0; i < kIlp; i++) {
        g_part[blockIdx.x * kRPerChunk + j[i]] =
            make_float4(binter[i], bS[i], __int_as_float(bidx[i]), 0.f);
    }
    __shared__ bool s_second;
    __threadfence();
    if (tid == 0) {
        unsigned prev = atomicAdd(&g_sync[slot], 1u);
        s_second = (prev == 1u);
        if (s_second) g_sync[slot] = 0u;   // reset for next graph replay
    }
    __syncthreads();
    if (!s_second) return;                 // first arrival is done

    // ---- merge with the other half (sibling's writes visible: its fence
    // preceded its atomic; our L1 holds no stale copies — first read this
    // launch and L1 is flushed per launch) ----
    const int sib = (slot << 1) | (half ^ 1);
    float cnt = 0.f, ce_s = 0.f, acc_s = 0.f, sl1_s = 0.f;
#pragma unroll
    for (int i = 0; i < kIlp; i++) {
        float4 o = g_part[sib * kRPerChunk + j[i]];
        float bi_lo, bS_lo, bi_up, bS_up; int id_lo, id_up;
        if (half == 1) {       // we are upper; sibling is lower
            bi_lo = o.x; bS_lo = o.y; id_lo = __float_as_int(o.z);
            bi_up = binter[i]; bS_up = bS[i]; id_up = bidx[i];
        } else {
            bi_lo = binter[i]; bS_lo = bS[i]; id_lo = bidx[i];
            bi_up = o.x; bS_up = o.y; id_up = __float_as_int(o.z);
        }
        // strict >: ties keep the lower half (smaller t) = first occurrence
        bool upd = bi_up * bS_lo > bi_lo * bS_up;
        float bi = upd ? bi_up : bi_lo;
        float bs = upd ? bS_up : bS_lo;
        int   bx = upd ? id_up : id_lo;

        float den = bs - bi;               // identical fl ops to reference
        float iou = bi / den;              // exact IEEE divide
        if (iou > kIouTh) {
            cnt += 1.f;
            // CE + accuracy over C=81 logits
            const float* p = rcnn_cls + (size_t)(b * kR + r[i]) * kC;
            float m = p[0];
            int am = 0;
            for (int c = 1; c < kC; ++c) {
                float v = p[c];
                if (v > m) { m = v; am = c; }
            }
            float s = 0.f;
            for (int c = 0; c < kC; ++c) s += expf(p[c] - m);
            int label = classes[b * kT + bx];
            ce_s += -(p[label] - m - logf(s));
            acc_s += (am == label) ? 1.f : 0.f;

            // Smooth-L1 vs stride-rounded offsets
            float4 gb = bboxes[b * kT + bx];
            float r0 = rintf(gb.x * 0.0625f) * 16.f;  // jnp.round = RN-even
            float r1 = rintf(gb.y * 0.0625f) * 16.f;
            float r2 = rintf(gb.z * 0.0625f) * 16.f;
            float r3 = rintf(gb.w * 0.0625f) * 16.f;
            float h = r2 - r0; h = (h == 0.f) ? 1.f : h;
            float w = r3 - r1; w = (w == 0.f) ? 1.f : w;
            float4 pr = rcnn_reg[b * kR + r[i]];
            float t0 = (gb.x - r0) / h, t1 = (gb.y - r1) / w;
            float t2 = (gb.z - r2) / h, t3 = (gb.w - r3) / w;
            float d;
            d = fabsf(pr.x - t0); sl1_s += (d < 1.f) ? 0.5f * d * d : d - 0.5f;
            d = fabsf(pr.y - t1); sl1_s += (d < 1.f) ? 0.5f * d * d : d - 0.5f;
            d = fabsf(pr.z - t2); sl1_s += (d < 1.f) ? 0.5f * d * d : d - 0.5f;
            d = fabsf(pr.w - t3); sl1_s += (d < 1.f) ? 0.5f * d * d : d - 0.5f;
        }
    }

    // ---- deterministic block reduction (4 warps) ----
    __shared__ float s_red[kThreads / 32][4];
    cnt = warp_sum(cnt); ce_s = warp_sum(ce_s);
    acc_s = warp_sum(acc_s); sl1_s = warp_sum(sl1_s);
    int wid = tid >> 5, lid = tid & 31;
    if (lid == 0) {
        s_red[wid][0] = cnt; s_red[wid][1] = ce_s;
        s_red[wid][2] = acc_s; s_red[wid][3] = sl1_s;
    }
    __syncthreads();
    if (tid == 0) {
        float v0 = 0.f, v1 = 0.f, v2 = 0.f, v3 = 0.f;
#pragma unroll
        for (int k = 0; k < kThreads / 32; ++k) {
            v0 += s_red[k][0]; v1 += s_red[k][1];
            v2 += s_red[k][2]; v3 += s_red[k][3];
        }
        g_red[slot][0] = v0; g_red[slot][1] = v1;
        g_red[slot][2] = v2; g_red[slot][3] = v3;
    }

    // ---- fused finalize: last of the 512 merge blocks ----
    __shared__ bool s_last;
    if (tid == 0) {
        __threadfence();
        unsigned prev = atomicAdd(&g_done, 1u);
        s_last = (prev == (unsigned)(kMergeSlots - 1));
    }
    __syncthreads();
    if (!s_last) return;

    float v0 = 0.f, v1 = 0.f, v2 = 0.f, v3 = 0.f;
#pragma unroll
    for (int k = 0; k < kMergeSlots / kThreads; ++k) {
        int idx = tid + k * kThreads;
        const volatile float* gp = &g_red[idx][0];
        v0 += gp[0]; v1 += gp[1]; v2 += gp[2]; v3 += gp[3];
    }
    v0 = warp_sum(v0); v1 = warp_sum(v1); v2 = warp_sum(v2); v3 = warp_sum(v3);
    __shared__ float s_fin[kThreads / 32][4];
    if (lid == 0) {
        s_fin[wid][0] = v0; s_fin[wid][1] = v1;
        s_fin[wid][2] = v2; s_fin[wid][3] = v3;
    }
    __syncthreads();
    if (tid == 0) {
        float npos = 0.f, ce = 0.f, acc = 0.f, sl1 = 0.f;
        for (int k = 0; k < kThreads / 32; ++k) {
            npos += s_fin[k][0]; ce += s_fin[k][1];
            acc += s_fin[k][2]; sl1 += s_fin[k][3];
        }
        float denom = fmaxf(npos, 1.f);
        bool has = npos > 0.f;
        out[0] = has ? ce / denom : 0.f;   // cls_loss
        out[1] = has ? sl1 / denom : 0.f;  // reg_loss
        out[2] = has ? acc / denom : 0.f;  // accuracy
        g_done = 0;                         // reset for next graph replay
    }
}

extern "C" void kernel_launch(void* const* d_in, const int* in_sizes, int n_in,
                              void* d_out, int out_size) {
    // metadata order: nms_reg, nms_cls (unused), rcnn_reg, rcnn_cls, bboxes, classes
    const float4* nms_reg  = (const float4*)d_in[0];
    const float4* rcnn_reg = (const float4*)d_in[2];
    const float*  rcnn_cls = (const float*)d_in[3];
    const float4* bboxes   = (const float4*)d_in[4];
    const int*    classes  = (const int*)d_in[5];
    (void)in_sizes; (void)n_in; (void)out_size;

    rcnn_main<<<kNBlocks, kThreads>>>(nms_reg, rcnn_reg, rcnn_cls, bboxes, classes,
                                      (float*)d_out);
}

// round 5
// speedup vs baseline: 1.1159x; 1.1159x over previous
#include <cuda_runtime.h>

// Problem constants (match reference module)
namespace {
constexpr int kB = 32, kT = 200, kR = 4096, kC = 81;
constexpr float kIouTh = 0.7f;
constexpr int kThreads = 128;                   // 4 warps/block
constexpr int kBlocksPerB = kR / kThreads;      // 32 chunks per batch
constexpr int kNBlocks = kB * kBlocksPerB;      // 1024 -> 6.92/SM, max 7 (balanced)
}

// Per-block partials: [npos, ce_sum, acc_sum, sl1_sum]
__device__ float g_partials[kNBlocks][4];
__device__ unsigned int g_done = 0;             // reset to 0 by last block each launch

__device__ __forceinline__ float warp_sum(float v) {
#pragma unroll
    for (int o = 16; o > 0; o >>= 1) v += __shfl_down_sync(0xffffffffu, v, o);
    return v;
}

__global__ __launch_bounds__(kThreads) void rcnn_main(
    const float4* __restrict__ nms_reg,   // [B,R,4]
    const float4* __restrict__ rcnn_reg,  // [B,R,4]
    const float*  __restrict__ rcnn_cls,  // [B,R,C]
    const float4* __restrict__ bboxes,    // [B,T,4]
    const int*    __restrict__ classes,   // [B,T]
    float* __restrict__ out)              // [3]
{
    __shared__ float4 s_box[kT];
    __shared__ float  s_area[kT];
    __shared__ int    s_cls[kT];

    const int b = blockIdx.x / kBlocksPerB;
    const int chunk = blockIdx.x % kBlocksPerB;
    const int tid = threadIdx.x;

    for (int i = tid; i < kT; i += kThreads) {
        float4 bb = bboxes[b * kT + i];
        s_box[i] = bb;
        s_area[i] = (bb.z - bb.x) * (bb.w - bb.y);
        s_cls[i] = classes[b * kT + i];
    }
    __syncthreads();

    // Contiguous mapping: positives (r < T) cluster into the first ~2 chunks
    // of each batch, so the heavy softmax epilogue runs SIMD-dense in a few
    // warps instead of 1-lane-sparse in every warp on the chip.
    const int r = chunk * kThreads + tid;

    const float4 a = nms_reg[b * kR + r];
    const float areaA = (a.z - a.x) * (a.w - a.y);
    float binter = 0.f;   // all-zero IoUs -> argmax = 0 (first occurrence)
    float bden   = 1.f;
    int   bidx   = 0;

    // ---- IoU argmax over T GT boxes (division-free rational compare) ----
    // iw left unclamped: a negative iw makes inter <= 0, which can never win
    // (binter >= 0, bden > 0, den > 0); any selected inter is therefore > 0
    // and the stored (inter, den) match the reference's fl ops exactly.
#pragma unroll 8
    for (int t = 0; t < kT; ++t) {
        float4 bb = s_box[t];
        float  ab = s_area[t];
        float tt = fmaxf(a.x, bb.x);
        float ll = fmaxf(a.y, bb.y);
        float bo = fminf(a.z, bb.z);
        float rr = fminf(a.w, bb.w);
        float ih = fmaxf(bo - tt, 0.f);
        float iw = rr - ll;
        float inter = ih * iw;
        float den = (areaA + ab) - inter;    // left-assoc, matches reference
        // inter/den > binter/bden  <=>  inter*bden > binter*den
        bool upd = inter * bden > binter * den;
        binter = upd ? inter : binter;
        bden   = upd ? den   : bden;
        bidx   = upd ? t     : bidx;
    }

    // ---- per-thread loss contribution if positive ----
    float cnt = 0.f, ce_s = 0.f, acc_s = 0.f, sl1_s = 0.f;
    float iou = binter / bden;               // exact IEEE divide, ref-compatible
    if (iou > kIouTh) {
        cnt = 1.f;

        // Cross-entropy + argmax accuracy over C=81 logits
        const float* p = rcnn_cls + (size_t)(b * kR + r) * kC;
        float m = p[0];
        int am = 0;
        for (int c = 1; c < kC; ++c) {
            float v = p[c];
            if (v > m) { m = v; am = c; }    // strict > keeps first occurrence
        }
        float s = 0.f;
        for (int c = 0; c < kC; ++c) s += expf(p[c] - m);
        int label = s_cls[bidx];
        ce_s = -(p[label] - m - logf(s));
        acc_s = (am == label) ? 1.f : 0.f;

        // Smooth-L1 regression vs stride-rounded offsets
        float4 gb = s_box[bidx];
        float r0 = rintf(gb.x * 0.0625f) * 16.f;   // jnp.round = RN-even = rintf
        float r1 = rintf(gb.y * 0.0625f) * 16.f;
        float r2 = rintf(gb.z * 0.0625f) * 16.f;
        float r3 = rintf(gb.w * 0.0625f) * 16.f;
        float h = r2 - r0; h = (h == 0.f) ? 1.f : h;
        float w = r3 - r1; w = (w == 0.f) ? 1.f : w;
        float4 pr = rcnn_reg[b * kR + r];
        float t0 = (gb.x - r0) / h, t1 = (gb.y - r1) / w;
        float t2 = (gb.z - r2) / h, t3 = (gb.w - r3) / w;
        float d;
        d = fabsf(pr.x - t0); sl1_s += (d < 1.f) ? 0.5f * d * d : d - 0.5f;
        d = fabsf(pr.y - t1); sl1_s += (d < 1.f) ? 0.5f * d * d : d - 0.5f;
        d = fabsf(pr.z - t2); sl1_s += (d < 1.f) ? 0.5f * d * d : d - 0.5f;
        d = fabsf(pr.w - t3); sl1_s += (d < 1.f) ? 0.5f * d * d : d - 0.5f;
    }

    // ---- deterministic block reduction (4 warps) ----
    __shared__ float s_red[kThreads / 32][4];
    cnt = warp_sum(cnt); ce_s = warp_sum(ce_s);
    acc_s = warp_sum(acc_s); sl1_s = warp_sum(sl1_s);
    int wid = tid >> 5, lid = tid & 31;
    if (lid == 0) {
        s_red[wid][0] = cnt; s_red[wid][1] = ce_s;
        s_red[wid][2] = acc_s; s_red[wid][3] = sl1_s;
    }
    __syncthreads();
    if (tid == 0) {
        float v0 = 0.f, v1 = 0.f, v2 = 0.f, v3 = 0.f;
#pragma unroll
        for (int k = 0; k < kThreads / 32; ++k) {
            v0 += s_red[k][0]; v1 += s_red[k][1];
            v2 += s_red[k][2]; v3 += s_red[k][3];
        }
        g_partials[blockIdx.x][0] = v0;
        g_partials[blockIdx.x][1] = v1;
        g_partials[blockIdx.x][2] = v2;
        g_partials[blockIdx.x][3] = v3;
    }

    // ---- fused finalize: last block to finish reduces all partials ----
    __shared__ bool s_last;
    if (tid == 0) {
        __threadfence();
        unsigned int prev = atomicAdd(&g_done, 1u);
        s_last = (prev == (unsigned)(kNBlocks - 1));
    }
    __syncthreads();
    if (!s_last) return;

    float v0 = 0.f, v1 = 0.f, v2 = 0.f, v3 = 0.f;
#pragma unroll
    for (int k = 0; k < kNBlocks / kThreads; ++k) {
        int idx = tid + k * kThreads;
        const volatile float* gp = &g_partials[idx][0];
        v0 += gp[0]; v1 += gp[1]; v2 += gp[2]; v3 += gp[3];
    }
    v0 = warp_sum(v0); v1 = warp_sum(v1); v2 = warp_sum(v2); v3 = warp_sum(v3);
    __shared__ float s_fin[kThreads / 32][4];
    if (lid == 0) {
        s_fin[wid][0] = v0; s_fin[wid][1] = v1;
        s_fin[wid][2] = v2; s_fin[wid][3] = v3;
    }
    __syncthreads();
    if (tid == 0) {
        float npos = 0.f, ce = 0.f, acc = 0.f, sl1 = 0.f;
        for (int k = 0; k < kThreads / 32; ++k) {
            npos += s_fin[k][0]; ce += s_fin[k][1];
            acc += s_fin[k][2]; sl1 += s_fin[k][3];
        }
        float denom = fmaxf(npos, 1.f);
        bool has = npos > 0.f;
        out[0] = has ? ce / denom : 0.f;   // cls_loss
        out[1] = has ? sl1 / denom : 0.f;  // reg_loss (sum of per-coord means)
        out[2] = has ? acc / denom : 0.f;  // accuracy
        g_done = 0;                         // reset for next graph replay
    }
}

extern "C" void kernel_launch(void* const* d_in, const int* in_sizes, int n_in,
                              void* d_out, int out_size) {
    // metadata order: nms_reg, nms_cls (unused), rcnn_reg, rcnn_cls, bboxes, classes
    const float4* nms_reg  = (const float4*)d_in[0];
    const float4* rcnn_reg = (const float4*)d_in[2];
    const float*  rcnn_cls = (const float*)d_in[3];
    const float4* bboxes   = (const float4*)d_in[4];
    const int*    classes  = (const int*)d_in[5];
    (void)in_sizes; (void)n_in; (void)out_size;

    rcnn_main<<<kNBlocks, kThreads>>>(nms_reg, rcnn_reg, rcnn_cls, bboxes, classes,
                                      (float*)d_out);
}